// round 3
// baseline (speedup 1.0000x reference)
#include <cuda_runtime.h>

#define MULc 16
#define Dc 4
#define S0c 8
#define S1c 8
#define SOUTc 8
#define P3c 8
#define P4c 4
#define NPATH (P3c + P4c)       // 12
#define NPAD 13                  // padded path dim (bank-conflict avoidance)

#define EPB 16
#define NTHREADS 256

__device__ __forceinline__ float4 f4fma(float s, float4 v, float4 a) {
    a.x = fmaf(s, v.x, a.x);
    a.y = fmaf(s, v.y, a.y);
    a.z = fmaf(s, v.z, a.z);
    a.w = fmaf(s, v.w, a.w);
    return a;
}

__global__ __launch_bounds__(NTHREADS) void tp_kernel(
    const float* __restrict__ x0, const int* __restrict__ i0,
    const float* __restrict__ x1, const float* __restrict__ C3,
    const float* __restrict__ C4, const int* __restrict__ p3,
    const int* __restrict__ p4, float* __restrict__ out, int E)
{
    __shared__ float  sC3[P3c * 64];        // 2 KB
    __shared__ float  sC4[P4c * 256];       // 4 KB
    __shared__ int    sp3[P3c * 3];
    __shared__ int    sp4[P4c * 4];
    __shared__ float4 sW4[EPB][NPAD][4];    // 13.3 KB  W rows (i-major, k in vec)
    __shared__ float4 sx1[EPB][S1c];        // 2 KB

    const int tid = threadIdx.x;

    for (int t = tid; t < P3c * 64; t += NTHREADS) sC3[t] = C3[t];
    for (int t = tid; t < P4c * 256; t += NTHREADS) sC4[t] = C4[t];
    if (tid < P3c * 3) sp3[tid] = p3[tid];
    if (tid < P4c * 4) sp4[tid] = p4[tid];

    const int eL = tid >> 4;
    const int u  = tid & 15;
    const int e  = blockIdx.x * EPB + eL;
    const bool valid = (e < E);

    if (valid && u < S1c)
        sx1[eL][u] = reinterpret_cast<const float4*>(x1 + (size_t)e * (S1c * Dc))[u];
    __syncthreads();

    // ---- W build: thread (ps, i) computes row i of W for paths ps, 4+ps, 8+ps
    if (valid) {
        const int bi = u & 3;     // i (row of W)
        const int ps = u >> 2;    // path slot

        #pragma unroll
        for (int r = 0; r < 2; r++) {
            const int p = r * 4 + ps;
            const float4 b = sx1[eL][sp3[p * 3 + 1]];
            const float4* c3 = reinterpret_cast<const float4*>(sC3 + p * 64 + bi * 16);
            float4 w = make_float4(0.f, 0.f, 0.f, 0.f);
            w = f4fma(b.x, c3[0], w);
            w = f4fma(b.y, c3[1], w);
            w = f4fma(b.z, c3[2], w);
            w = f4fma(b.w, c3[3], w);
            sW4[eL][p][bi] = w;
        }
        {
            const int q = ps;
            const float4 b = sx1[eL][sp4[q * 4 + 1]];
            const float4 c = sx1[eL][sp4[q * 4 + 2]];
            const float4* c4 = reinterpret_cast<const float4*>(sC4 + q * 256 + bi * 64);
            float4 w = make_float4(0.f, 0.f, 0.f, 0.f);
            w = f4fma(b.x * c.x, c4[0],  w);
            w = f4fma(b.x * c.y, c4[1],  w);
            w = f4fma(b.x * c.z, c4[2],  w);
            w = f4fma(b.x * c.w, c4[3],  w);
            w = f4fma(b.y * c.x, c4[4],  w);
            w = f4fma(b.y * c.y, c4[5],  w);
            w = f4fma(b.y * c.z, c4[6],  w);
            w = f4fma(b.y * c.w, c4[7],  w);
            w = f4fma(b.z * c.x, c4[8],  w);
            w = f4fma(b.z * c.y, c4[9],  w);
            w = f4fma(b.z * c.z, c4[10], w);
            w = f4fma(b.z * c.w, c4[11], w);
            w = f4fma(b.w * c.x, c4[12], w);
            w = f4fma(b.w * c.y, c4[13], w);
            w = f4fma(b.w * c.z, c4[14], w);
            w = f4fma(b.w * c.w, c4[15], w);
            sW4[eL][P3c + q][bi] = w;
        }
    }
    __syncthreads();

    if (!valid) return;

    int s3[P3c], z3[P3c], s4[P4c], z4[P4c];
    #pragma unroll
    for (int p = 0; p < P3c; p++) { s3[p] = sp3[p * 3 + 0]; z3[p] = sp3[p * 3 + 2]; }
    #pragma unroll
    for (int p = 0; p < P4c; p++) { s4[p] = sp4[p * 4 + 0]; z4[p] = sp4[p * 4 + 3]; }

    const float4* arow = reinterpret_cast<const float4*>(
        x0 + (size_t)__ldg(&i0[e]) * (S0c * MULc * Dc));
    float4* orow = reinterpret_cast<float4*>(out + (size_t)e * (SOUTc * MULc * Dc));

    #pragma unroll
    for (int z = 0; z < SOUTc; z++) {
        float4 r = make_float4(0.f, 0.f, 0.f, 0.f);
        #pragma unroll
        for (int p = 0; p < P3c; p++) {
            if (z3[p] == z) {
                const float4 av = __ldg(&arow[s3[p] * MULc + u]);
                const float4* w = sW4[eL][p];
                r = f4fma(av.x, w[0], r);
                r = f4fma(av.y, w[1], r);
                r = f4fma(av.z, w[2], r);
                r = f4fma(av.w, w[3], r);
            }
        }
        #pragma unroll
        for (int p = 0; p < P4c; p++) {
            if (z4[p] == z) {
                const float4 av = __ldg(&arow[s4[p] * MULc + u]);
                const float4* w = sW4[eL][P3c + p];
                r = f4fma(av.x, w[0], r);
                r = f4fma(av.y, w[1], r);
                r = f4fma(av.z, w[2], r);
                r = f4fma(av.w, w[3], r);
            }
        }
        orow[z * MULc + u] = r;
    }
}

extern "C" void kernel_launch(void* const* d_in, const int* in_sizes, int n_in,
                              void* d_out, int out_size) {
    const float* x0 = (const float*)d_in[0];
    const int*   i0 = (const int*)d_in[1];
    const float* x1 = (const float*)d_in[2];
    const float* C3 = (const float*)d_in[3];
    const float* C4 = (const float*)d_in[4];
    const int*   p3 = (const int*)d_in[5];
    const int*   p4 = (const int*)d_in[6];

    const int E = in_sizes[1];
    const int blocks = (E + EPB - 1) / EPB;
    tp_kernel<<<blocks, NTHREADS>>>(x0, i0, x1, C3, C4, p3, p4, (float*)d_out, E);
}

// round 5
// speedup vs baseline: 1.2464x; 1.2464x over previous
#include <cuda_runtime.h>

#define MULc 16
#define Dc 4
#define S0c 8
#define S1c 8
#define SOUTc 8
#define P3c 8
#define P4c 4
#define NPATH (P3c + P4c)

#define EPB 64
#define NTHREADS 256
#define WSTRIDE 193                    // floats per edge in sW (12*16 + 1 pad)
#define SW_FLOATS (EPB * WSTRIDE)
#define SX1_FLOATS (EPB * S1c * Dc)
#define SMEM_BYTES ((SW_FLOATS + SX1_FLOATS) * 4)

__global__ __launch_bounds__(NTHREADS) void tp_kernel(
    const float* __restrict__ x0, const int* __restrict__ i0,
    const float* __restrict__ x1, const float* __restrict__ C3,
    const float* __restrict__ C4, const int* __restrict__ p3,
    const int* __restrict__ p4, float* __restrict__ out, int E)
{
    extern __shared__ float smem[];
    float* sW  = smem;                 // [EPB][WSTRIDE]
    float* sx1 = smem + SW_FLOATS;     // [EPB][32]

    const int tid  = threadIdx.x;
    const int base = blockIdx.x * EPB;
    int nE = E - base; if (nE > EPB) nE = EPB;

    // ---- stage x1 rows (contiguous, coalesced float4) ----
    {
        const float4* src = reinterpret_cast<const float4*>(x1 + (size_t)base * 32);
        float4* dst = reinterpret_cast<float4*>(sx1);
        for (int t = tid; t < nE * 8; t += NTHREADS) dst[t] = src[t];
    }
    __syncthreads();

    // ---- W build: path-specialized warps, C in registers ----
    {
        const int warp = tid >> 5, lane = tid & 31;
        const int g  = lane >> 4;          // half-warp select
        const int l  = lane & 15;          // (i,k) within 4x4
        const int wi = l >> 2, wk = l & 3;

        if (warp < 4) {
            // two 3-paths per warp: p = 2*warp + g, all nE edges
            const int p = warp * 2 + g;
            const int segb = __ldg(&p3[p * 3 + 1]);
            const float c0 = __ldg(&C3[p * 64 + wi * 16 + 0 + wk]);
            const float c1 = __ldg(&C3[p * 64 + wi * 16 + 4 + wk]);
            const float c2 = __ldg(&C3[p * 64 + wi * 16 + 8 + wk]);
            const float c3v = __ldg(&C3[p * 64 + wi * 16 + 12 + wk]);
            for (int e = 0; e < nE; e++) {
                const float* b = sx1 + e * 32 + segb * 4;
                float w = fmaf(b[0], c0, fmaf(b[1], c1, fmaf(b[2], c2, b[3] * c3v)));
                sW[e * WSTRIDE + p * 16 + l] = w;
            }
        } else {
            // one 4-path per warp: q = warp-4, edges split by half-warp
            const int q = warp - 4;
            const int segb = __ldg(&p4[q * 4 + 1]);
            const int segc = __ldg(&p4[q * 4 + 2]);
            float creg[16];
            #pragma unroll
            for (int j = 0; j < 4; j++)
                #pragma unroll
                for (int m = 0; m < 4; m++)
                    creg[j * 4 + m] = __ldg(&C4[q * 256 + wi * 64 + j * 16 + m * 4 + wk]);
            const int e0 = g * (EPB / 2);
            int e1 = e0 + (EPB / 2); if (e1 > nE) e1 = nE;
            for (int e = e0; e < e1; e++) {
                const float* b = sx1 + e * 32 + segb * 4;
                const float* c = sx1 + e * 32 + segc * 4;
                float w = 0.f;
                #pragma unroll
                for (int j = 0; j < 4; j++) {
                    float t = fmaf(c[0], creg[j * 4 + 0],
                              fmaf(c[1], creg[j * 4 + 1],
                              fmaf(c[2], creg[j * 4 + 2],
                                   c[3] * creg[j * 4 + 3])));
                    w = fmaf(b[j], t, w);
                }
                sW[e * WSTRIDE + (P3c + q) * 16 + l] = w;
            }
        }
    }
    __syncthreads();

    // ---- contrib: 4 threads per edge, 4 muls each (u = q + 4j) ----
    const int eL = tid >> 2;
    const int q  = tid & 3;
    const int e  = base + eL;
    if (e >= E) return;

    int s3[P3c], z3[P3c], s4[P4c], z4[P4c];
    #pragma unroll
    for (int p = 0; p < P3c; p++) { s3[p] = __ldg(&p3[p * 3 + 0]); z3[p] = __ldg(&p3[p * 3 + 2]); }
    #pragma unroll
    for (int p = 0; p < P4c; p++) { s4[p] = __ldg(&p4[p * 4 + 0]); z4[p] = __ldg(&p4[p * 4 + 3]); }

    const float4* arow = reinterpret_cast<const float4*>(
        x0 + (size_t)__ldg(&i0[e]) * (S0c * MULc * Dc));
    float4* orow = reinterpret_cast<float4*>(out + (size_t)e * (SOUTc * MULc * Dc));
    const float* wbase = sW + eL * WSTRIDE;

    #pragma unroll
    for (int z = 0; z < SOUTc; z++) {
        float4 r0 = make_float4(0.f, 0.f, 0.f, 0.f);
        float4 r1 = r0, r2 = r0, r3 = r0;

        #pragma unroll
        for (int pp = 0; pp < NPATH; pp++) {
            const int zp = (pp < P3c) ? z3[pp] : z4[pp - P3c];
            if (zp == z) {
                const int sp = (pp < P3c) ? s3[pp] : s4[pp - P3c];
                const float* w = wbase + pp * 16;
                const float w0 = w[0],  w1 = w[1],  w2 = w[2],  w3 = w[3];
                const float w4 = w[4],  w5 = w[5],  w6 = w[6],  w7 = w[7];
                const float w8 = w[8],  w9 = w[9],  wa = w[10], wb = w[11];
                const float wc = w[12], wd = w[13], we = w[14], wf = w[15];

                const float4 a0 = __ldg(&arow[sp * MULc + q]);
                const float4 a1 = __ldg(&arow[sp * MULc + q + 4]);
                const float4 a2 = __ldg(&arow[sp * MULc + q + 8]);
                const float4 a3 = __ldg(&arow[sp * MULc + q + 12]);

                r0.x = fmaf(a0.x, w0, fmaf(a0.y, w4, fmaf(a0.z, w8, fmaf(a0.w, wc, r0.x))));
                r0.y = fmaf(a0.x, w1, fmaf(a0.y, w5, fmaf(a0.z, w9, fmaf(a0.w, wd, r0.y))));
                r0.z = fmaf(a0.x, w2, fmaf(a0.y, w6, fmaf(a0.z, wa, fmaf(a0.w, we, r0.z))));
                r0.w = fmaf(a0.x, w3, fmaf(a0.y, w7, fmaf(a0.z, wb, fmaf(a0.w, wf, r0.w))));

                r1.x = fmaf(a1.x, w0, fmaf(a1.y, w4, fmaf(a1.z, w8, fmaf(a1.w, wc, r1.x))));
                r1.y = fmaf(a1.x, w1, fmaf(a1.y, w5, fmaf(a1.z, w9, fmaf(a1.w, wd, r1.y))));
                r1.z = fmaf(a1.x, w2, fmaf(a1.y, w6, fmaf(a1.z, wa, fmaf(a1.w, we, r1.z))));
                r1.w = fmaf(a1.x, w3, fmaf(a1.y, w7, fmaf(a1.z, wb, fmaf(a1.w, wf, r1.w))));

                r2.x = fmaf(a2.x, w0, fmaf(a2.y, w4, fmaf(a2.z, w8, fmaf(a2.w, wc, r2.x))));
                r2.y = fmaf(a2.x, w1, fmaf(a2.y, w5, fmaf(a2.z, w9, fmaf(a2.w, wd, r2.y))));
                r2.z = fmaf(a2.x, w2, fmaf(a2.y, w6, fmaf(a2.z, wa, fmaf(a2.w, we, r2.z))));
                r2.w = fmaf(a2.x, w3, fmaf(a2.y, w7, fmaf(a2.z, wb, fmaf(a2.w, wf, r2.w))));

                r3.x = fmaf(a3.x, w0, fmaf(a3.y, w4, fmaf(a3.z, w8, fmaf(a3.w, wc, r3.x))));
                r3.y = fmaf(a3.x, w1, fmaf(a3.y, w5, fmaf(a3.z, w9, fmaf(a3.w, wd, r3.y))));
                r3.z = fmaf(a3.x, w2, fmaf(a3.y, w6, fmaf(a3.z, wa, fmaf(a3.w, we, r3.z))));
                r3.w = fmaf(a3.x, w3, fmaf(a3.y, w7, fmaf(a3.z, wb, fmaf(a3.w, wf, r3.w))));
            }
        }
        orow[z * MULc + q]      = r0;
        orow[z * MULc + q + 4]  = r1;
        orow[z * MULc + q + 8]  = r2;
        orow[z * MULc + q + 12] = r3;
    }
}

extern "C" void kernel_launch(void* const* d_in, const int* in_sizes, int n_in,
                              void* d_out, int out_size) {
    const float* x0 = (const float*)d_in[0];
    const int*   i0 = (const int*)d_in[1];
    const float* x1 = (const float*)d_in[2];
    const float* C3 = (const float*)d_in[3];
    const float* C4 = (const float*)d_in[4];
    const int*   p3 = (const int*)d_in[5];
    const int*   p4 = (const int*)d_in[6];

    const int E = in_sizes[1];
    cudaFuncSetAttribute(tp_kernel, cudaFuncAttributeMaxDynamicSharedMemorySize, SMEM_BYTES);
    const int blocks = (E + EPB - 1) / EPB;
    tp_kernel<<<blocks, NTHREADS, SMEM_BYTES>>>(x0, i0, x1, C3, C4, p3, p4, (float*)d_out, E);
}

// round 6
// speedup vs baseline: 1.5969x; 1.2812x over previous
#include <cuda_runtime.h>

#define MULc 16
#define Dc 4
#define S0c 8
#define S1c 8
#define SOUTc 8
#define P3c 8
#define P4c 4
#define NPATH (P3c + P4c)

#define EPB 32
#define NTHREADS 128
#define WSTRIDE 193                    // floats per edge in sW (12*16 + 1 pad)
#define SW_FLOATS (EPB * WSTRIDE)
#define SX1_FLOATS (EPB * S1c * Dc)
#define SMEM_BYTES ((SW_FLOATS + SX1_FLOATS) * 4)

__global__ __launch_bounds__(NTHREADS) void tp_kernel(
    const float* __restrict__ x0, const int* __restrict__ i0,
    const float* __restrict__ x1, const float* __restrict__ C3,
    const float* __restrict__ C4, const int* __restrict__ p3,
    const int* __restrict__ p4, float* __restrict__ out, int E)
{
    extern __shared__ float smem[];
    float* sW  = smem;                 // [EPB][WSTRIDE]
    float* sx1 = smem + SW_FLOATS;     // [EPB][32]

    const int tid  = threadIdx.x;
    const int base = blockIdx.x * EPB;
    int nE = E - base; if (nE > EPB) nE = EPB;

    // ---- stage x1 rows (contiguous, coalesced float4) ----
    {
        const float4* src = reinterpret_cast<const float4*>(x1 + (size_t)base * 32);
        float4* dst = reinterpret_cast<float4*>(sx1);
        for (int t = tid; t < nE * 8; t += NTHREADS) dst[t] = src[t];
    }
    __syncthreads();

    // ---- W build: uniform work per warp ----
    // Each warp w: 3-paths p = 2w+g (g = half-warp) over all edges,
    //              then 4-path q = w with edges split by half-warp.
    {
        const int warp = tid >> 5, lane = tid & 31;
        const int g  = lane >> 4;          // half-warp select
        const int l  = lane & 15;          // (i,k) within 4x4
        const int wi = l >> 2, wk = l & 3;

        // --- two 3-paths per warp ---
        {
            const int p = warp * 2 + g;
            const int segb = __ldg(&p3[p * 3 + 1]);
            const float c0  = __ldg(&C3[p * 64 + wi * 16 + 0  + wk]);
            const float c1  = __ldg(&C3[p * 64 + wi * 16 + 4  + wk]);
            const float c2  = __ldg(&C3[p * 64 + wi * 16 + 8  + wk]);
            const float c3v = __ldg(&C3[p * 64 + wi * 16 + 12 + wk]);
            #pragma unroll 4
            for (int e = 0; e < nE; e++) {
                const float* b = sx1 + e * 32 + segb * 4;
                float w = fmaf(b[0], c0, fmaf(b[1], c1, fmaf(b[2], c2, b[3] * c3v)));
                sW[e * WSTRIDE + p * 16 + l] = w;
            }
        }
        // --- one 4-path per warp, edges split by half-warp ---
        {
            const int q = warp;
            const int segb = __ldg(&p4[q * 4 + 1]);
            const int segc = __ldg(&p4[q * 4 + 2]);
            float creg[16];
            #pragma unroll
            for (int j = 0; j < 4; j++)
                #pragma unroll
                for (int m = 0; m < 4; m++)
                    creg[j * 4 + m] = __ldg(&C4[q * 256 + wi * 64 + j * 16 + m * 4 + wk]);
            const int e0 = g * (EPB / 2);
            int e1 = e0 + (EPB / 2); if (e1 > nE) e1 = nE;
            #pragma unroll 2
            for (int e = e0; e < e1; e++) {
                const float* b = sx1 + e * 32 + segb * 4;
                const float* c = sx1 + e * 32 + segc * 4;
                float w = 0.f;
                #pragma unroll
                for (int j = 0; j < 4; j++) {
                    float t = fmaf(c[0], creg[j * 4 + 0],
                              fmaf(c[1], creg[j * 4 + 1],
                              fmaf(c[2], creg[j * 4 + 2],
                                   c[3] * creg[j * 4 + 3])));
                    w = fmaf(b[j], t, w);
                }
                sW[e * WSTRIDE + (P3c + q) * 16 + l] = w;
            }
        }
    }
    __syncthreads();

    // ---- contrib: 4 threads per edge, 4 muls each (u = q + 4j) ----
    const int eL = tid >> 2;
    const int q  = tid & 3;
    const int e  = base + eL;
    if (e >= E) return;

    int s3[P3c], z3[P3c], s4[P4c], z4[P4c];
    #pragma unroll
    for (int p = 0; p < P3c; p++) { s3[p] = __ldg(&p3[p * 3 + 0]); z3[p] = __ldg(&p3[p * 3 + 2]); }
    #pragma unroll
    for (int p = 0; p < P4c; p++) { s4[p] = __ldg(&p4[p * 4 + 0]); z4[p] = __ldg(&p4[p * 4 + 3]); }

    const float4* arow = reinterpret_cast<const float4*>(
        x0 + (size_t)__ldg(&i0[e]) * (S0c * MULc * Dc));
    float4* orow = reinterpret_cast<float4*>(out + (size_t)e * (SOUTc * MULc * Dc));
    const float* wbase = sW + eL * WSTRIDE;

    #pragma unroll
    for (int z = 0; z < SOUTc; z++) {
        float4 r0 = make_float4(0.f, 0.f, 0.f, 0.f);
        float4 r1 = r0, r2 = r0, r3 = r0;

        #pragma unroll
        for (int pp = 0; pp < NPATH; pp++) {
            const int zp = (pp < P3c) ? z3[pp] : z4[pp - P3c];
            if (zp == z) {
                const int sp = (pp < P3c) ? s3[pp] : s4[pp - P3c];
                const float* w = wbase + pp * 16;
                const float w0 = w[0],  w1 = w[1],  w2 = w[2],  w3 = w[3];
                const float w4 = w[4],  w5 = w[5],  w6 = w[6],  w7 = w[7];
                const float w8 = w[8],  w9 = w[9],  wa = w[10], wb = w[11];
                const float wc = w[12], wd = w[13], we = w[14], wf = w[15];

                const float4 a0 = __ldg(&arow[sp * MULc + q]);
                const float4 a1 = __ldg(&arow[sp * MULc + q + 4]);
                const float4 a2 = __ldg(&arow[sp * MULc + q + 8]);
                const float4 a3 = __ldg(&arow[sp * MULc + q + 12]);

                r0.x = fmaf(a0.x, w0, fmaf(a0.y, w4, fmaf(a0.z, w8, fmaf(a0.w, wc, r0.x))));
                r0.y = fmaf(a0.x, w1, fmaf(a0.y, w5, fmaf(a0.z, w9, fmaf(a0.w, wd, r0.y))));
                r0.z = fmaf(a0.x, w2, fmaf(a0.y, w6, fmaf(a0.z, wa, fmaf(a0.w, we, r0.z))));
                r0.w = fmaf(a0.x, w3, fmaf(a0.y, w7, fmaf(a0.z, wb, fmaf(a0.w, wf, r0.w))));

                r1.x = fmaf(a1.x, w0, fmaf(a1.y, w4, fmaf(a1.z, w8, fmaf(a1.w, wc, r1.x))));
                r1.y = fmaf(a1.x, w1, fmaf(a1.y, w5, fmaf(a1.z, w9, fmaf(a1.w, wd, r1.y))));
                r1.z = fmaf(a1.x, w2, fmaf(a1.y, w6, fmaf(a1.z, wa, fmaf(a1.w, we, r1.z))));
                r1.w = fmaf(a1.x, w3, fmaf(a1.y, w7, fmaf(a1.z, wb, fmaf(a1.w, wf, r1.w))));

                r2.x = fmaf(a2.x, w0, fmaf(a2.y, w4, fmaf(a2.z, w8, fmaf(a2.w, wc, r2.x))));
                r2.y = fmaf(a2.x, w1, fmaf(a2.y, w5, fmaf(a2.z, w9, fmaf(a2.w, wd, r2.y))));
                r2.z = fmaf(a2.x, w2, fmaf(a2.y, w6, fmaf(a2.z, wa, fmaf(a2.w, we, r2.z))));
                r2.w = fmaf(a2.x, w3, fmaf(a2.y, w7, fmaf(a2.z, wb, fmaf(a2.w, wf, r2.w))));

                r3.x = fmaf(a3.x, w0, fmaf(a3.y, w4, fmaf(a3.z, w8, fmaf(a3.w, wc, r3.x))));
                r3.y = fmaf(a3.x, w1, fmaf(a3.y, w5, fmaf(a3.z, w9, fmaf(a3.w, wd, r3.y))));
                r3.z = fmaf(a3.x, w2, fmaf(a3.y, w6, fmaf(a3.z, wa, fmaf(a3.w, we, r3.z))));
                r3.w = fmaf(a3.x, w3, fmaf(a3.y, w7, fmaf(a3.z, wb, fmaf(a3.w, wf, r3.w))));
            }
        }
        orow[z * MULc + q]      = r0;
        orow[z * MULc + q + 4]  = r1;
        orow[z * MULc + q + 8]  = r2;
        orow[z * MULc + q + 12] = r3;
    }
}

extern "C" void kernel_launch(void* const* d_in, const int* in_sizes, int n_in,
                              void* d_out, int out_size) {
    const float* x0 = (const float*)d_in[0];
    const int*   i0 = (const int*)d_in[1];
    const float* x1 = (const float*)d_in[2];
    const float* C3 = (const float*)d_in[3];
    const float* C4 = (const float*)d_in[4];
    const int*   p3 = (const int*)d_in[5];
    const int*   p4 = (const int*)d_in[6];

    const int E = in_sizes[1];
    cudaFuncSetAttribute(tp_kernel, cudaFuncAttributeMaxDynamicSharedMemorySize, SMEM_BYTES);
    const int blocks = (E + EPB - 1) / EPB;
    tp_kernel<<<blocks, NTHREADS, SMEM_BYTES>>>(x0, i0, x1, C3, C4, p3, p4, (float*)d_out, E);
}

// round 7
// speedup vs baseline: 1.6128x; 1.0100x over previous
#include <cuda_runtime.h>

#define MULc 16
#define Dc 4
#define S0c 8
#define S1c 8
#define SOUTc 8
#define P3c 8
#define P4c 4
#define NPATH (P3c + P4c)

#define EPB 8
#define NTHREADS 32
#define WSTRIDE 193                    // 12*16 + 1 pad (8 edges -> 8 distinct banks)

__global__ __launch_bounds__(NTHREADS) void tp_kernel(
    const float* __restrict__ x0, const int* __restrict__ i0,
    const float* __restrict__ x1, const float* __restrict__ C3,
    const float* __restrict__ C4, const int* __restrict__ p3,
    const int* __restrict__ p4, float* __restrict__ out, int E)
{
    __shared__ float sW[EPB * WSTRIDE];    // 6176 B
    __shared__ float sx1[EPB * 32];        // 1024 B

    const int tid  = threadIdx.x;
    const int base = blockIdx.x * EPB;
    int nE = E - base; if (nE > EPB) nE = EPB;

    // ---- stage x1 rows (8 edges x 32 floats = 64 float4; 2 per lane) ----
    {
        const float4* src = reinterpret_cast<const float4*>(x1 + (size_t)base * 32);
        float4* dst = reinterpret_cast<float4*>(sx1);
        const int lim = nE * 8;
        for (int t = tid; t < lim; t += NTHREADS) dst[t] = src[t];
    }
    __syncwarp();

    // ---- W build (warp-local, C in registers) ----
    {
        const int g  = (tid >> 4) & 1;     // half-warp
        const int l  = tid & 15;           // (i,k)
        const int wi = l >> 2, wk = l & 3;

        // 3-paths: 4 passes, half-warps handle p = 2*pass + g
        #pragma unroll
        for (int pass = 0; pass < 4; pass++) {
            const int p = pass * 2 + g;
            const int segb = __ldg(&p3[p * 3 + 1]);
            const float c0  = __ldg(&C3[p * 64 + wi * 16 + 0  + wk]);
            const float c1  = __ldg(&C3[p * 64 + wi * 16 + 4  + wk]);
            const float c2  = __ldg(&C3[p * 64 + wi * 16 + 8  + wk]);
            const float c3v = __ldg(&C3[p * 64 + wi * 16 + 12 + wk]);
            for (int e = 0; e < nE; e++) {
                const float* b = sx1 + e * 32 + segb * 4;
                sW[e * WSTRIDE + p * 16 + l] =
                    fmaf(b[0], c0, fmaf(b[1], c1, fmaf(b[2], c2, b[3] * c3v)));
            }
        }
        // 4-paths: 2 passes, half-warps handle q = 2*pass + g
        #pragma unroll
        for (int pass = 0; pass < 2; pass++) {
            const int q = pass * 2 + g;
            const int segb = __ldg(&p4[q * 4 + 1]);
            const int segc = __ldg(&p4[q * 4 + 2]);
            float creg[16];
            #pragma unroll
            for (int j = 0; j < 4; j++)
                #pragma unroll
                for (int m = 0; m < 4; m++)
                    creg[j * 4 + m] = __ldg(&C4[q * 256 + wi * 64 + j * 16 + m * 4 + wk]);
            for (int e = 0; e < nE; e++) {
                const float* b = sx1 + e * 32 + segb * 4;
                const float* c = sx1 + e * 32 + segc * 4;
                float w = 0.f;
                #pragma unroll
                for (int j = 0; j < 4; j++) {
                    float t = fmaf(c[0], creg[j * 4 + 0],
                              fmaf(c[1], creg[j * 4 + 1],
                              fmaf(c[2], creg[j * 4 + 2],
                                   c[3] * creg[j * 4 + 3])));
                    w = fmaf(b[j], t, w);
                }
                sW[e * WSTRIDE + (P3c + q) * 16 + l] = w;
            }
        }
    }
    __syncwarp();

    // ---- contrib: 4 lanes per edge, 4 muls each (u = q + 4j) ----
    const int eL = tid >> 2;
    const int q  = tid & 3;
    const int e  = base + eL;
    if (e >= E) return;

    int s3[P3c], z3[P3c], s4[P4c], z4[P4c];
    #pragma unroll
    for (int p = 0; p < P3c; p++) { s3[p] = __ldg(&p3[p * 3 + 0]); z3[p] = __ldg(&p3[p * 3 + 2]); }
    #pragma unroll
    for (int p = 0; p < P4c; p++) { s4[p] = __ldg(&p4[p * 4 + 0]); z4[p] = __ldg(&p4[p * 4 + 3]); }

    const float4* arow = reinterpret_cast<const float4*>(
        x0 + (size_t)__ldg(&i0[e]) * (S0c * MULc * Dc));
    float4* orow = reinterpret_cast<float4*>(out + (size_t)e * (SOUTc * MULc * Dc));
    const float* wbase = sW + eL * WSTRIDE;

    #pragma unroll
    for (int z = 0; z < SOUTc; z++) {
        float4 r0 = make_float4(0.f, 0.f, 0.f, 0.f);
        float4 r1 = r0, r2 = r0, r3 = r0;

        #pragma unroll
        for (int pp = 0; pp < NPATH; pp++) {
            const int zp = (pp < P3c) ? z3[pp] : z4[pp - P3c];
            if (zp == z) {
                const int sp = (pp < P3c) ? s3[pp] : s4[pp - P3c];
                const float* w = wbase + pp * 16;
                const float w0 = w[0],  w1 = w[1],  w2 = w[2],  w3 = w[3];
                const float w4 = w[4],  w5 = w[5],  w6 = w[6],  w7 = w[7];
                const float w8 = w[8],  w9 = w[9],  wa = w[10], wb = w[11];
                const float wc = w[12], wd = w[13], we = w[14], wf = w[15];

                const float4 a0 = __ldg(&arow[sp * MULc + q]);
                const float4 a1 = __ldg(&arow[sp * MULc + q + 4]);
                const float4 a2 = __ldg(&arow[sp * MULc + q + 8]);
                const float4 a3 = __ldg(&arow[sp * MULc + q + 12]);

                r0.x = fmaf(a0.x, w0, fmaf(a0.y, w4, fmaf(a0.z, w8, fmaf(a0.w, wc, r0.x))));
                r0.y = fmaf(a0.x, w1, fmaf(a0.y, w5, fmaf(a0.z, w9, fmaf(a0.w, wd, r0.y))));
                r0.z = fmaf(a0.x, w2, fmaf(a0.y, w6, fmaf(a0.z, wa, fmaf(a0.w, we, r0.z))));
                r0.w = fmaf(a0.x, w3, fmaf(a0.y, w7, fmaf(a0.z, wb, fmaf(a0.w, wf, r0.w))));

                r1.x = fmaf(a1.x, w0, fmaf(a1.y, w4, fmaf(a1.z, w8, fmaf(a1.w, wc, r1.x))));
                r1.y = fmaf(a1.x, w1, fmaf(a1.y, w5, fmaf(a1.z, w9, fmaf(a1.w, wd, r1.y))));
                r1.z = fmaf(a1.x, w2, fmaf(a1.y, w6, fmaf(a1.z, wa, fmaf(a1.w, we, r1.z))));
                r1.w = fmaf(a1.x, w3, fmaf(a1.y, w7, fmaf(a1.z, wb, fmaf(a1.w, wf, r1.w))));

                r2.x = fmaf(a2.x, w0, fmaf(a2.y, w4, fmaf(a2.z, w8, fmaf(a2.w, wc, r2.x))));
                r2.y = fmaf(a2.x, w1, fmaf(a2.y, w5, fmaf(a2.z, w9, fmaf(a2.w, wd, r2.y))));
                r2.z = fmaf(a2.x, w2, fmaf(a2.y, w6, fmaf(a2.z, wa, fmaf(a2.w, we, r2.z))));
                r2.w = fmaf(a2.x, w3, fmaf(a2.y, w7, fmaf(a2.z, wb, fmaf(a2.w, wf, r2.w))));

                r3.x = fmaf(a3.x, w0, fmaf(a3.y, w4, fmaf(a3.z, w8, fmaf(a3.w, wc, r3.x))));
                r3.y = fmaf(a3.x, w1, fmaf(a3.y, w5, fmaf(a3.z, w9, fmaf(a3.w, wd, r3.y))));
                r3.z = fmaf(a3.x, w2, fmaf(a3.y, w6, fmaf(a3.z, wa, fmaf(a3.w, we, r3.z))));
                r3.w = fmaf(a3.x, w3, fmaf(a3.y, w7, fmaf(a3.z, wb, fmaf(a3.w, wf, r3.w))));
            }
        }
        orow[z * MULc + q]      = r0;
        orow[z * MULc + q + 4]  = r1;
        orow[z * MULc + q + 8]  = r2;
        orow[z * MULc + q + 12] = r3;
    }
}

extern "C" void kernel_launch(void* const* d_in, const int* in_sizes, int n_in,
                              void* d_out, int out_size) {
    const float* x0 = (const float*)d_in[0];
    const int*   i0 = (const int*)d_in[1];
    const float* x1 = (const float*)d_in[2];
    const float* C3 = (const float*)d_in[3];
    const float* C4 = (const float*)d_in[4];
    const int*   p3 = (const int*)d_in[5];
    const int*   p4 = (const int*)d_in[6];

    const int E = in_sizes[1];
    const int blocks = (E + EPB - 1) / EPB;
    tp_kernel<<<blocks, NTHREADS>>>(x0, i0, x1, C3, C4, p3, p4, (float*)d_out, E);
}

// round 8
// speedup vs baseline: 1.6554x; 1.0264x over previous
#include <cuda_runtime.h>

#define MULc 16
#define Dc 4
#define S0c 8
#define S1c 8
#define SOUTc 8
#define P3c 8
#define P4c 4
#define NPATH (P3c + P4c)

#define EPB 8
#define NTHREADS 32
#define WSTRIDE 196                    // == 4 (mod 32): 8 edges' float4 rows tile all 32 banks

__device__ __forceinline__ float4 f4fma(float s, float4 v, float4 a) {
    a.x = fmaf(s, v.x, a.x);
    a.y = fmaf(s, v.y, a.y);
    a.z = fmaf(s, v.z, a.z);
    a.w = fmaf(s, v.w, a.w);
    return a;
}

__global__ __launch_bounds__(NTHREADS) void tp_kernel(
    const float* __restrict__ x0, const int* __restrict__ i0,
    const float* __restrict__ x1, const float* __restrict__ C3,
    const float* __restrict__ C4, const int* __restrict__ p3,
    const int* __restrict__ p4, float* __restrict__ out, int E)
{
    __shared__ __align__(16) float sW[EPB * WSTRIDE];   // 6272 B
    __shared__ __align__(16) float sx1[EPB * 32];       // 1024 B

    const int tid  = threadIdx.x;
    const int base = blockIdx.x * EPB;
    int nE = E - base; if (nE > EPB) nE = EPB;

    // ---- stage x1 rows ----
    {
        const float4* src = reinterpret_cast<const float4*>(x1 + (size_t)base * 32);
        float4* dst = reinterpret_cast<float4*>(sx1);
        const int lim = nE * 8;
        for (int t = tid; t < lim; t += NTHREADS) dst[t] = src[t];
    }
    __syncwarp();

    // ---- W build (warp-local, C in registers, b/c as float4 broadcast) ----
    {
        const int g  = (tid >> 4) & 1;     // half-warp
        const int l  = tid & 15;           // (i,k)
        const int wi = l >> 2, wk = l & 3;

        // 3-paths: 4 passes, half-warps handle p = 2*pass + g
        #pragma unroll
        for (int pass = 0; pass < 4; pass++) {
            const int p = pass * 2 + g;
            const int segb = __ldg(&p3[p * 3 + 1]);
            const float c0  = __ldg(&C3[p * 64 + wi * 16 + 0  + wk]);
            const float c1  = __ldg(&C3[p * 64 + wi * 16 + 4  + wk]);
            const float c2  = __ldg(&C3[p * 64 + wi * 16 + 8  + wk]);
            const float c3v = __ldg(&C3[p * 64 + wi * 16 + 12 + wk]);
            for (int e = 0; e < nE; e++) {
                const float4 b = *reinterpret_cast<const float4*>(sx1 + e * 32 + segb * 4);
                sW[e * WSTRIDE + p * 16 + l] =
                    fmaf(b.x, c0, fmaf(b.y, c1, fmaf(b.z, c2, b.w * c3v)));
            }
        }
        // 4-paths: 2 passes, half-warps handle q = 2*pass + g
        #pragma unroll
        for (int pass = 0; pass < 2; pass++) {
            const int q = pass * 2 + g;
            const int segb = __ldg(&p4[q * 4 + 1]);
            const int segc = __ldg(&p4[q * 4 + 2]);
            float creg[16];
            #pragma unroll
            for (int j = 0; j < 4; j++)
                #pragma unroll
                for (int m = 0; m < 4; m++)
                    creg[j * 4 + m] = __ldg(&C4[q * 256 + wi * 64 + j * 16 + m * 4 + wk]);
            for (int e = 0; e < nE; e++) {
                const float4 b = *reinterpret_cast<const float4*>(sx1 + e * 32 + segb * 4);
                const float4 c = *reinterpret_cast<const float4*>(sx1 + e * 32 + segc * 4);
                float w;
                {
                    float t0 = fmaf(c.x, creg[0],  fmaf(c.y, creg[1],  fmaf(c.z, creg[2],  c.w * creg[3])));
                    float t1 = fmaf(c.x, creg[4],  fmaf(c.y, creg[5],  fmaf(c.z, creg[6],  c.w * creg[7])));
                    float t2 = fmaf(c.x, creg[8],  fmaf(c.y, creg[9],  fmaf(c.z, creg[10], c.w * creg[11])));
                    float t3 = fmaf(c.x, creg[12], fmaf(c.y, creg[13], fmaf(c.z, creg[14], c.w * creg[15])));
                    w = fmaf(b.x, t0, fmaf(b.y, t1, fmaf(b.z, t2, b.w * t3)));
                }
                sW[e * WSTRIDE + (P3c + q) * 16 + l] = w;
            }
        }
    }
    __syncwarp();

    // ---- contrib: 4 lanes per edge, 4 muls each (u = q + 4j) ----
    const int eL = tid >> 2;
    const int q  = tid & 3;
    const int e  = base + eL;
    if (e >= E) return;

    // packed metadata: s | (z << 16)
    int m3[P3c], m4[P4c];
    #pragma unroll
    for (int p = 0; p < P3c; p++)
        m3[p] = __ldg(&p3[p * 3 + 0]) | (__ldg(&p3[p * 3 + 2]) << 16);
    #pragma unroll
    for (int p = 0; p < P4c; p++)
        m4[p] = __ldg(&p4[p * 4 + 0]) | (__ldg(&p4[p * 4 + 3]) << 16);

    const float4* arow = reinterpret_cast<const float4*>(
        x0 + (size_t)__ldg(&i0[e]) * (S0c * MULc * Dc));
    float4* orow = reinterpret_cast<float4*>(out + (size_t)e * (SOUTc * MULc * Dc));
    const float* wbase = sW + eL * WSTRIDE;

    #pragma unroll
    for (int z = 0; z < SOUTc; z++) {
        float4 r0 = make_float4(0.f, 0.f, 0.f, 0.f);
        float4 r1 = r0, r2 = r0, r3 = r0;

        #pragma unroll
        for (int pp = 0; pp < NPATH; pp++) {
            const int meta = (pp < P3c) ? m3[pp] : m4[pp - P3c];
            if ((meta >> 16) == z) {
                const int sp = meta & 0xffff;
                const float4* wv = reinterpret_cast<const float4*>(wbase + pp * 16);
                const float4 W0 = wv[0], W1 = wv[1], W2 = wv[2], W3 = wv[3];

                const float4 a0 = __ldg(&arow[sp * MULc + q]);
                const float4 a1 = __ldg(&arow[sp * MULc + q + 4]);
                const float4 a2 = __ldg(&arow[sp * MULc + q + 8]);
                const float4 a3 = __ldg(&arow[sp * MULc + q + 12]);

                r0 = f4fma(a0.x, W0, r0); r0 = f4fma(a0.y, W1, r0);
                r0 = f4fma(a0.z, W2, r0); r0 = f4fma(a0.w, W3, r0);

                r1 = f4fma(a1.x, W0, r1); r1 = f4fma(a1.y, W1, r1);
                r1 = f4fma(a1.z, W2, r1); r1 = f4fma(a1.w, W3, r1);

                r2 = f4fma(a2.x, W0, r2); r2 = f4fma(a2.y, W1, r2);
                r2 = f4fma(a2.z, W2, r2); r2 = f4fma(a2.w, W3, r2);

                r3 = f4fma(a3.x, W0, r3); r3 = f4fma(a3.y, W1, r3);
                r3 = f4fma(a3.z, W2, r3); r3 = f4fma(a3.w, W3, r3);
            }
        }
        orow[z * MULc + q]      = r0;
        orow[z * MULc + q + 4]  = r1;
        orow[z * MULc + q + 8]  = r2;
        orow[z * MULc + q + 12] = r3;
    }
}

extern "C" void kernel_launch(void* const* d_in, const int* in_sizes, int n_in,
                              void* d_out, int out_size) {
    const float* x0 = (const float*)d_in[0];
    const int*   i0 = (const int*)d_in[1];
    const float* x1 = (const float*)d_in[2];
    const float* C3 = (const float*)d_in[3];
    const float* C4 = (const float*)d_in[4];
    const int*   p3 = (const int*)d_in[5];
    const int*   p4 = (const int*)d_in[6];

    const int E = in_sizes[1];
    const int blocks = (E + EPB - 1) / EPB;
    tp_kernel<<<blocks, NTHREADS>>>(x0, i0, x1, C3, C4, p3, p4, (float*)d_out, E);
}